// round 4
// baseline (speedup 1.0000x reference)
#include <cuda_runtime.h>
#include <cstdint>

// Problem constants
#define B_   16
#define Q_   900
#define C_   91
#define T_   100
#define BT_  1600           // B_*T_
#define BQ_  14400          // B_*Q_
#define COST_ELEMS 23040000 // BQ_*BT_
#define ROWS_PER_BLK 8
#define COST_THREADS 256

// ---------------------------------------------------------------------------
// Kernel 1: build full cost matrix [B, Q, B*T] into d_out[0 .. COST_ELEMS)
// cost = L1(cxcywh) - sigmoid(logit[row, tgt_label[j]]) - GIoU(xyxy)
// ---------------------------------------------------------------------------
__global__ __launch_bounds__(COST_THREADS)
void cost_kernel(const float* __restrict__ logits,      // [BQ_, C_]
                 const float* __restrict__ pred_boxes,  // [BQ_, 4]
                 const int*   __restrict__ tgt_labels,  // [BT_]
                 const float* __restrict__ tgt_boxes,   // [BT_, 4]
                 float* __restrict__ out)                // [BQ_, BT_]
{
    __shared__ float4 s_tb[BT_];          // target cxcywh
    __shared__ int    s_tl[BT_];          // target labels
    __shared__ float  s_prob[ROWS_PER_BLK][C_ + 1];  // sigmoid probs per row

    const int tid = threadIdx.x;
    const int base_i = blockIdx.x * ROWS_PER_BLK;

    // stage targets
    const float4* tb4 = reinterpret_cast<const float4*>(tgt_boxes);
    for (int j = tid; j < BT_; j += COST_THREADS) {
        s_tb[j] = tb4[j];
        s_tl[j] = tgt_labels[j];
    }
    // stage sigmoid probs for this block's rows
    for (int k = tid; k < ROWS_PER_BLK * C_; k += COST_THREADS) {
        int rr = k / C_, c = k % C_;
        float x = logits[(size_t)(base_i + rr) * C_ + c];
        s_prob[rr][c] = 1.0f / (1.0f + expf(-x));
    }
    __syncthreads();

    #pragma unroll
    for (int rr = 0; rr < ROWS_PER_BLK; rr++) {
        const int i = base_i + rr;
        float4 pb = reinterpret_cast<const float4*>(pred_boxes)[i];
        const float pcx = pb.x, pcy = pb.y, pw = pb.z, ph = pb.w;
        const float px0 = pcx - 0.5f * pw, py0 = pcy - 0.5f * ph;
        const float px1 = pcx + 0.5f * pw, py1 = pcy + 0.5f * ph;
        const float parea = (px1 - px0) * (py1 - py0);
        float* orow = out + (size_t)i * BT_;
        const float* pr = s_prob[rr];

        for (int j = tid; j < BT_; j += COST_THREADS) {
            float4 tb = s_tb[j];
            // L1 on cxcywh
            float l1 = fabsf(pcx - tb.x) + fabsf(pcy - tb.y)
                     + fabsf(pw - tb.z) + fabsf(ph - tb.w);
            // target xyxy + area
            float tx0 = tb.x - 0.5f * tb.z, ty0 = tb.y - 0.5f * tb.w;
            float tx1 = tb.x + 0.5f * tb.z, ty1 = tb.y + 0.5f * tb.w;
            float tarea = (tx1 - tx0) * (ty1 - ty0);
            // intersection
            float ltx = fmaxf(px0, tx0), lty = fmaxf(py0, ty0);
            float rbx = fminf(px1, tx1), rby = fminf(py1, ty1);
            float iw = fmaxf(rbx - ltx, 0.0f), ih = fmaxf(rby - lty, 0.0f);
            float inter = iw * ih;
            float uni = parea + tarea - inter;
            float iou = inter / uni;
            // enclosing box
            float ex0 = fminf(px0, tx0), ey0 = fminf(py0, ty0);
            float ex1 = fmaxf(px1, tx1), ey1 = fmaxf(py1, ty1);
            float ew = fmaxf(ex1 - ex0, 0.0f), eh = fmaxf(ey1 - ey0, 0.0f);
            float earea = ew * eh;
            float giou = iou - (earea - uni) / earea;

            orow[j] = l1 - pr[s_tl[j]] - giou;
        }
    }
}

// ---------------------------------------------------------------------------
// Kernel 2: greedy matcher. One block per batch image.
// Maintains per-row cached minima over unmatched cols (< T_ only — the
// reference masks cols >= T_ to +inf). Each of the 100 steps:
//   1. packed-u64 argmin over 900 row minima (tie-break = lowest row)
//   2. eliminate (r*, c*), emit
//   3. rescan only rows whose cached min col == c* (warp per row, tie = lowest col)
// Float ordering via monotonic uint key; packed (key<<32)|idx gives argmin
// with exact flat-index tie-break semantics matching jnp.argmin.
// ---------------------------------------------------------------------------
__device__ __forceinline__ unsigned fkey(float f) {
    unsigned b = __float_as_uint(f);
    return (b & 0x80000000u) ? ~b : (b | 0x80000000u);
}

#define MATCHED_KEY 0xFFFFFFFFu

__global__ __launch_bounds__(1024)
void greedy_kernel(const float* __restrict__ cost,  // [BQ_, BT_] (reads cols 0..T_-1)
                   float* __restrict__ rows_out,    // [B_, T_]
                   float* __restrict__ cols_out)    // [B_, T_]
{
    const int b = blockIdx.x;
    const int tid = threadIdx.x;
    const int lane = tid & 31;
    const int wid = tid >> 5;
    const float* Cb = cost + (size_t)b * Q_ * BT_;

    __shared__ unsigned s_key[Q_];
    __shared__ int s_col[Q_];
    __shared__ unsigned char s_colm[T_];
    __shared__ unsigned long long s_best;
    __shared__ int s_cand[Q_];
    __shared__ int s_ncand;
    __shared__ int s_cstar;

    if (tid < T_) s_colm[tid] = 0;
    if (tid == 0) { s_best = ~0ull; s_ncand = 0; }

    // init per-row minima over cols [0, T_)
    if (tid < Q_) {
        const float4* rp = reinterpret_cast<const float4*>(Cb + (size_t)tid * BT_);
        float best = __int_as_float(0x7f800000);  // +inf
        int bc = 0;
        #pragma unroll
        for (int k = 0; k < T_ / 4; k++) {
            float4 v = rp[k];
            if (v.x < best) { best = v.x; bc = 4 * k; }
            if (v.y < best) { best = v.y; bc = 4 * k + 1; }
            if (v.z < best) { best = v.z; bc = 4 * k + 2; }
            if (v.w < best) { best = v.w; bc = 4 * k + 3; }
        }
        s_key[tid] = fkey(best);
        s_col[tid] = bc;
    }
    __syncthreads();

    for (int step = 0; step < T_; step++) {
        // ---- phase 1: global argmin over row minima ----
        unsigned long long v = ~0ull;
        if (tid < Q_)
            v = ((unsigned long long)s_key[tid] << 32) | (unsigned)tid;
        #pragma unroll
        for (int o = 16; o; o >>= 1) {
            unsigned long long w = __shfl_down_sync(0xFFFFFFFFu, v, o);
            if (w < v) v = w;
        }
        if (lane == 0) atomicMin(&s_best, v);
        __syncthreads();                                  // S1

        int r = (int)(s_best & 0xFFFFFFFFu);
        if (tid == 0) {
            int c = s_col[r];
            s_cstar = c;
            s_colm[c] = 1;
            s_key[r] = MATCHED_KEY;
            s_ncand = 0;
            rows_out[b * T_ + step] = (float)r;
            cols_out[b * T_ + step] = (float)c;
        }
        __syncthreads();                                  // S2

        if (tid == 0) s_best = ~0ull;  // safe: nobody touches s_best until next phase 1
        const int cstar = s_cstar;

        // ---- phase 2: collect rows that must rescan ----
        if (tid < Q_ && s_key[tid] != MATCHED_KEY && s_col[tid] == cstar) {
            int idx = atomicAdd(&s_ncand, 1);
            s_cand[idx] = tid;
        }
        __syncthreads();                                  // S3

        // ---- phase 3: warp-per-row rescan over unmatched cols ----
        const int n = s_ncand;
        for (int cnd = wid; cnd < n; cnd += 32) {
            int rr = s_cand[cnd];
            const float* rowp = Cb + (size_t)rr * BT_;
            unsigned long long bp = ~0ull;
            #pragma unroll
            for (int j = lane; j < T_; j += 32) {
                if (!s_colm[j]) {
                    unsigned long long p =
                        ((unsigned long long)fkey(rowp[j]) << 32) | (unsigned)j;
                    if (p < bp) bp = p;
                }
            }
            #pragma unroll
            for (int o = 16; o; o >>= 1) {
                unsigned long long w = __shfl_down_sync(0xFFFFFFFFu, bp, o);
                if (w < bp) bp = w;
            }
            if (lane == 0) {
                s_key[rr] = (unsigned)(bp >> 32);
                s_col[rr] = (int)(bp & 0xFFFFFFFFu);
            }
        }
        __syncthreads();                                  // S4
    }
}

// ---------------------------------------------------------------------------
extern "C" void kernel_launch(void* const* d_in, const int* in_sizes, int n_in,
                              void* d_out, int out_size)
{
    const float* logits     = (const float*)d_in[0];  // [16,900,91]
    const float* pred_boxes = (const float*)d_in[1];  // [16,900,4]
    const int*   tgt_labels = (const int*)  d_in[2];  // [16,100]
    const float* tgt_boxes  = (const float*)d_in[3];  // [16,100,4]
    float* out = (float*)d_out;

    cost_kernel<<<BQ_ / ROWS_PER_BLK, COST_THREADS>>>(
        logits, pred_boxes, tgt_labels, tgt_boxes, out);

    greedy_kernel<<<B_, 1024>>>(
        out, out + COST_ELEMS, out + COST_ELEMS + B_ * T_);
}

// round 5
// speedup vs baseline: 1.5087x; 1.5087x over previous
#include <cuda_runtime.h>
#include <cstdint>

#define B_   16
#define Q_   900
#define C_   91
#define T_   100
#define BT_  1600
#define BQ_  14400
#define COST_ELEMS 23040000
#define ROWS_PER_BLK 8
#define COST_THREADS 256
#define GT   256   // greedy threads (8 warps)

// dynamic smem layout for cost kernel
#define OFF_TB   0                       // float4[1600] cxcywh
#define OFF_XY   25600                   // float4[1600] xyxy
#define OFF_TA   51200                   // float [1600] area
#define OFF_TL   57600                   // int   [1600] labels
#define OFF_PR   64000                   // float [ROWS_PER_BLK][92] sigmoid probs
#define SMEM_COST (OFF_PR + ROWS_PER_BLK * 92 * 4)

// ---------------------------------------------------------------------------
// Kernel 1: cost matrix [BQ_, BT_]
// ---------------------------------------------------------------------------
__global__ __launch_bounds__(COST_THREADS)
void cost_kernel(const float* __restrict__ logits,
                 const float* __restrict__ pred_boxes,
                 const int*   __restrict__ tgt_labels,
                 const float* __restrict__ tgt_boxes,
                 float* __restrict__ out)
{
    extern __shared__ char dyn[];
    float4* s_tb = (float4*)(dyn + OFF_TB);
    float4* s_xy = (float4*)(dyn + OFF_XY);
    float*  s_ta = (float*) (dyn + OFF_TA);
    int*    s_tl = (int*)   (dyn + OFF_TL);
    float*  s_pr = (float*) (dyn + OFF_PR);   // [ROWS_PER_BLK][92]

    const int tid = threadIdx.x;
    const int base_i = blockIdx.x * ROWS_PER_BLK;

    const float4* tb4 = reinterpret_cast<const float4*>(tgt_boxes);
    for (int j = tid; j < BT_; j += COST_THREADS) {
        float4 t = tb4[j];
        s_tb[j] = t;
        float x0 = t.x - 0.5f * t.z, y0 = t.y - 0.5f * t.w;
        float x1 = t.x + 0.5f * t.z, y1 = t.y + 0.5f * t.w;
        s_xy[j] = make_float4(x0, y0, x1, y1);
        s_ta[j] = (x1 - x0) * (y1 - y0);
        s_tl[j] = tgt_labels[j];
    }
    for (int k = tid; k < ROWS_PER_BLK * C_; k += COST_THREADS) {
        int rr = k / C_, c = k % C_;
        float x = logits[(size_t)(base_i + rr) * C_ + c];
        s_pr[rr * 92 + c] = 1.0f / (1.0f + expf(-x));
    }
    __syncthreads();

    #pragma unroll
    for (int rr = 0; rr < ROWS_PER_BLK; rr++) {
        const int i = base_i + rr;
        float4 pb = reinterpret_cast<const float4*>(pred_boxes)[i];
        const float pcx = pb.x, pcy = pb.y, pw = pb.z, ph = pb.w;
        const float px0 = pcx - 0.5f * pw, py0 = pcy - 0.5f * ph;
        const float px1 = pcx + 0.5f * pw, py1 = pcy + 0.5f * ph;
        const float parea = (px1 - px0) * (py1 - py0);
        float* orow = out + (size_t)i * BT_;
        const float* pr = s_pr + rr * 92;

        for (int j = tid; j < BT_; j += COST_THREADS) {
            float4 t = s_tb[j];
            float4 x = s_xy[j];
            float l1 = fabsf(pcx - t.x) + fabsf(pcy - t.y)
                     + fabsf(pw - t.z) + fabsf(ph - t.w);
            float ltx = fmaxf(px0, x.x), lty = fmaxf(py0, x.y);
            float rbx = fminf(px1, x.z), rby = fminf(py1, x.w);
            float inter = fmaxf(rbx - ltx, 0.0f) * fmaxf(rby - lty, 0.0f);
            float uni = parea + s_ta[j] - inter;
            float iou = inter / uni;
            float ex0 = fminf(px0, x.x), ey0 = fminf(py0, x.y);
            float ex1 = fmaxf(px1, x.z), ey1 = fmaxf(py1, x.w);
            float earea = (ex1 - ex0) * (ey1 - ey0);   // strictly positive: clip is identity
            float giou = iou - (earea - uni) / earea;
            orow[j] = l1 - pr[s_tl[j]] - giou;
        }
    }
}

// ---------------------------------------------------------------------------
// Kernel 2: greedy matcher with per-COLUMN min caching.
// packed = (fkey(v) << 32) | (row << 7) | col  -> lex compare == (value, row, col)
// which is exactly jnp.argmin's flat-index tie-break (row-major).
// Expected total column rescans over 100 steps: sum (100-s)/(900-s) ~= 6.
// ---------------------------------------------------------------------------
__device__ __forceinline__ unsigned fkey(float f) {
    unsigned b = __float_as_uint(f);
    return (b & 0x80000000u) ? ~b : (b | 0x80000000u);
}

__global__ __launch_bounds__(GT)
void greedy_kernel(const float* __restrict__ cost,
                   float* __restrict__ rows_out,
                   float* __restrict__ cols_out)
{
    const int b = blockIdx.x;
    const int tid = threadIdx.x;
    const int lane = tid & 31;
    const int wid = tid >> 5;
    const float* Cb = cost + (size_t)b * Q_ * BT_;

    __shared__ unsigned long long s_ckey[T_];   // per-column packed minima
    __shared__ unsigned char s_rowm[Q_];        // matched-row mask
    __shared__ int s_cand[T_];
    __shared__ int s_ncand;

    for (int i = tid; i < Q_; i += GT) s_rowm[i] = 0;
    if (tid < T_) s_ckey[tid] = ~0ull;
    if (tid == 0) s_ncand = 0;
    __syncthreads();

    // ---- init: per-column minima. warp w scans rows w, w+8, ...; lane owns
    // 4 consecutive cols (float4 load, coalesced 400B per warp-row). ----
    if (lane < 25) {
        const int c0 = lane * 4;
        unsigned long long m0 = ~0ull, m1 = ~0ull, m2 = ~0ull, m3 = ~0ull;
        for (int r = wid; r < Q_; r += 8) {
            float4 v = *reinterpret_cast<const float4*>(Cb + (size_t)r * BT_ + c0);
            unsigned rb = (unsigned)(r << 7);
            unsigned long long p;
            p = ((unsigned long long)fkey(v.x) << 32) | (rb | (c0 + 0)); if (p < m0) m0 = p;
            p = ((unsigned long long)fkey(v.y) << 32) | (rb | (c0 + 1)); if (p < m1) m1 = p;
            p = ((unsigned long long)fkey(v.z) << 32) | (rb | (c0 + 2)); if (p < m2) m2 = p;
            p = ((unsigned long long)fkey(v.w) << 32) | (rb | (c0 + 3)); if (p < m3) m3 = p;
        }
        atomicMin(&s_ckey[c0 + 0], m0);
        atomicMin(&s_ckey[c0 + 1], m1);
        atomicMin(&s_ckey[c0 + 2], m2);
        atomicMin(&s_ckey[c0 + 3], m3);
    }
    __syncthreads();

    for (int step = 0; step < T_; step++) {
        // ---- warp 0: argmin over 100 column minima + bookkeeping + candidates ----
        if (wid == 0) {
            unsigned long long p0 = ~0ull, p1 = ~0ull, p2 = ~0ull, p3 = ~0ull;
            if (lane < 25) {
                const int c0 = lane * 4;
                p0 = s_ckey[c0];     p1 = s_ckey[c0 + 1];
                p2 = s_ckey[c0 + 2]; p3 = s_ckey[c0 + 3];
            }
            unsigned long long m = p0;
            if (p1 < m) m = p1; if (p2 < m) m = p2; if (p3 < m) m = p3;
            #pragma unroll
            for (int o = 16; o; o >>= 1) {
                unsigned long long w = __shfl_xor_sync(0xFFFFFFFFu, m, o);
                if (w < m) m = w;
            }
            // all lanes now hold the global min
            const int r = (int)((m >> 7) & 0x3FFu);
            const int c = (int)(m & 0x7Fu);

            if (lane == 26) s_ncand = 0;
            __syncwarp();
            if (lane == 0) {
                s_rowm[r] = 1;
                s_ckey[c] = ~0ull;
                rows_out[b * T_ + step] = (float)r;
                cols_out[b * T_ + step] = (float)c;
            }
            // candidate columns: cached min row == r (and not the matched col itself)
            if (lane < 25) {
                if ((int)((p0 >> 7) & 0x3FFu) == r && (int)(p0 & 0x7Fu) != c)
                    s_cand[atomicAdd(&s_ncand, 1)] = (int)(p0 & 0x7Fu);
                if ((int)((p1 >> 7) & 0x3FFu) == r && (int)(p1 & 0x7Fu) != c)
                    s_cand[atomicAdd(&s_ncand, 1)] = (int)(p1 & 0x7Fu);
                if ((int)((p2 >> 7) & 0x3FFu) == r && (int)(p2 & 0x7Fu) != c)
                    s_cand[atomicAdd(&s_ncand, 1)] = (int)(p2 & 0x7Fu);
                if ((int)((p3 >> 7) & 0x3FFu) == r && (int)(p3 & 0x7Fu) != c)
                    s_cand[atomicAdd(&s_ncand, 1)] = (int)(p3 & 0x7Fu);
            }
        }
        __syncthreads();   // B1

        // ---- rescan invalidated columns (rare: ~6 total over all 100 steps) ----
        const int n = s_ncand;
        if (n > 0 && step != T_ - 1) {
            for (int k = wid; k < n; k += 8) {
                const int cc = s_cand[k];
                const float* colp = Cb + cc;
                unsigned long long best = ~0ull;
                for (int rr = lane; rr < Q_; rr += 32) {
                    if (!s_rowm[rr]) {
                        unsigned long long p =
                            ((unsigned long long)fkey(colp[(size_t)rr * BT_]) << 32)
                            | (unsigned)((rr << 7) | cc);
                        if (p < best) best = p;
                    }
                }
                #pragma unroll
                for (int o = 16; o; o >>= 1) {
                    unsigned long long w = __shfl_xor_sync(0xFFFFFFFFu, best, o);
                    if (w < best) best = w;
                }
                if (lane == 0) s_ckey[cc] = best;
            }
        }
        __syncthreads();   // B2 (loop end)
    }
}

// ---------------------------------------------------------------------------
extern "C" void kernel_launch(void* const* d_in, const int* in_sizes, int n_in,
                              void* d_out, int out_size)
{
    const float* logits     = (const float*)d_in[0];
    const float* pred_boxes = (const float*)d_in[1];
    const int*   tgt_labels = (const int*)  d_in[2];
    const float* tgt_boxes  = (const float*)d_in[3];
    float* out = (float*)d_out;

    cudaFuncSetAttribute(cost_kernel,
                         cudaFuncAttributeMaxDynamicSharedMemorySize, SMEM_COST);

    cost_kernel<<<BQ_ / ROWS_PER_BLK, COST_THREADS, SMEM_COST>>>(
        logits, pred_boxes, tgt_labels, tgt_boxes, out);

    greedy_kernel<<<B_, GT>>>(
        out, out + COST_ELEMS, out + COST_ELEMS + B_ * T_);
}

// round 6
// speedup vs baseline: 1.8745x; 1.2425x over previous
#include <cuda_runtime.h>
#include <cstdint>

#define B_   16
#define Q_   900
#define C_   91
#define T_   100
#define BT_  1600
#define BQ_  14400
#define COST_ELEMS 23040000
#define RPB  8
#define COST_THREADS 256

// dynamic smem layout for cost kernel
#define OFF_TB   0                       // float4[1600] cxcywh
#define OFF_XY   25600                   // float4[1600] xyxy
#define OFF_TA   51200                   // float [1600] area
#define OFF_TL   57600                   // int   [1600] labels
#define OFF_PR   64000                   // float [RPB][92] sigmoid probs
#define SMEM_COST (OFF_PR + RPB * 92 * 4)

// ---------------------------------------------------------------------------
// Kernel 1: cost matrix [BQ_, BT_].  Target-outer / rows-inner: per j the
// target is loaded once and 8 rows are computed from register constants.
// Arithmetic order is bit-identical to the previous passing kernel.
// ---------------------------------------------------------------------------
__global__ __launch_bounds__(COST_THREADS)
void cost_kernel(const float* __restrict__ logits,
                 const float* __restrict__ pred_boxes,
                 const int*   __restrict__ tgt_labels,
                 const float* __restrict__ tgt_boxes,
                 float* __restrict__ out)
{
    extern __shared__ char dyn[];
    float4* s_tb = (float4*)(dyn + OFF_TB);
    float4* s_xy = (float4*)(dyn + OFF_XY);
    float*  s_ta = (float*) (dyn + OFF_TA);
    int*    s_tl = (int*)   (dyn + OFF_TL);
    float*  s_pr = (float*) (dyn + OFF_PR);   // [RPB][92]

    const int tid = threadIdx.x;
    const int base_i = blockIdx.x * RPB;

    const float4* tb4 = reinterpret_cast<const float4*>(tgt_boxes);
    for (int j = tid; j < BT_; j += COST_THREADS) {
        float4 t = tb4[j];
        s_tb[j] = t;
        float x0 = t.x - 0.5f * t.z, y0 = t.y - 0.5f * t.w;
        float x1 = t.x + 0.5f * t.z, y1 = t.y + 0.5f * t.w;
        s_xy[j] = make_float4(x0, y0, x1, y1);
        s_ta[j] = (x1 - x0) * (y1 - y0);
        s_tl[j] = tgt_labels[j];
    }
    for (int k = tid; k < RPB * C_; k += COST_THREADS) {
        int rr = k / C_, c = k % C_;
        float x = logits[(size_t)(base_i + rr) * C_ + c];
        s_pr[rr * 92 + c] = 1.0f / (1.0f + expf(-x));
    }
    __syncthreads();

    // register-resident row constants
    float pcx[RPB], pcy[RPB], pw[RPB], ph[RPB];
    float px0[RPB], py0[RPB], px1[RPB], py1[RPB], pa[RPB];
    #pragma unroll
    for (int rr = 0; rr < RPB; rr++) {
        float4 pb = reinterpret_cast<const float4*>(pred_boxes)[base_i + rr];
        pcx[rr] = pb.x; pcy[rr] = pb.y; pw[rr] = pb.z; ph[rr] = pb.w;
        px0[rr] = pb.x - 0.5f * pb.z; py0[rr] = pb.y - 0.5f * pb.w;
        px1[rr] = pb.x + 0.5f * pb.z; py1[rr] = pb.y + 0.5f * pb.w;
        pa[rr]  = (px1[rr] - px0[rr]) * (py1[rr] - py0[rr]);
    }
    float* orow0 = out + (size_t)base_i * BT_;

    for (int j = tid; j < BT_; j += COST_THREADS) {
        float4 t = s_tb[j];
        float4 x = s_xy[j];
        float ta = s_ta[j];
        int lb = s_tl[j];
        #pragma unroll
        for (int rr = 0; rr < RPB; rr++) {
            float l1 = fabsf(pcx[rr] - t.x) + fabsf(pcy[rr] - t.y)
                     + fabsf(pw[rr] - t.z) + fabsf(ph[rr] - t.w);
            float ltx = fmaxf(px0[rr], x.x), lty = fmaxf(py0[rr], x.y);
            float rbx = fminf(px1[rr], x.z), rby = fminf(py1[rr], x.w);
            float inter = fmaxf(rbx - ltx, 0.0f) * fmaxf(rby - lty, 0.0f);
            float uni = pa[rr] + ta - inter;
            float iou = inter / uni;
            float ex0 = fminf(px0[rr], x.x), ey0 = fminf(py0[rr], x.y);
            float ex1 = fmaxf(px1[rr], x.z), ey1 = fmaxf(py1[rr], x.w);
            float earea = (ex1 - ex0) * (ey1 - ey0);
            float giou = iou - (earea - uni) / earea;
            orow0[(size_t)rr * BT_ + j] = l1 - s_pr[rr * 92 + lb] - giou;
        }
    }
}

// ---------------------------------------------------------------------------
// Kernel 2: greedy matcher. 1024-thread cooperative init of per-column
// minima, then warp 0 runs all 100 steps entirely in registers:
//   slot[s] (lanes 0..24, s<4): packed (fkey<<32)|(row<<7)|col for col lane*4+s
//   mrow: bit i set  <=>  row (lane + 32*i) already matched
// Argmin per step: 3 register compares + redux.min(key) + redux.min(tag).
// Tie-break identical to jnp.argmin flat order (key, then row, then col).
// ---------------------------------------------------------------------------
__device__ __forceinline__ unsigned fkey(float f) {
    unsigned b = __float_as_uint(f);
    return (b & 0x80000000u) ? ~b : (b | 0x80000000u);
}

__device__ __forceinline__ unsigned redux_min_u32(unsigned v) {
    unsigned d;
    asm("redux.sync.min.u32 %0, %1, 0xffffffff;" : "=r"(d) : "r"(v));
    return d;
}

#define FULLM 0xFFFFFFFFu

__global__ __launch_bounds__(1024)
void greedy_kernel(const float* __restrict__ cost,
                   float* __restrict__ rows_out,
                   float* __restrict__ cols_out)
{
    const int b = blockIdx.x;
    const int tid = threadIdx.x;
    const int lane = tid & 31;
    const int wid = tid >> 5;
    const float* Cb = cost + (size_t)b * Q_ * BT_;

    __shared__ unsigned long long s_ckey[T_];
    if (tid < T_) s_ckey[tid] = ~0ull;
    __syncthreads();

    // cooperative init: 32 warps stride rows; lane owns 4 consecutive cols
    if (lane < 25) {
        const int c0 = lane * 4;
        unsigned long long m0 = ~0ull, m1 = ~0ull, m2 = ~0ull, m3 = ~0ull;
        for (int r = wid; r < Q_; r += 32) {
            float4 v = *reinterpret_cast<const float4*>(Cb + (size_t)r * BT_ + c0);
            unsigned rb = (unsigned)(r << 7);
            unsigned long long p;
            p = ((unsigned long long)fkey(v.x) << 32) | (rb | (c0 + 0)); if (p < m0) m0 = p;
            p = ((unsigned long long)fkey(v.y) << 32) | (rb | (c0 + 1)); if (p < m1) m1 = p;
            p = ((unsigned long long)fkey(v.z) << 32) | (rb | (c0 + 2)); if (p < m2) m2 = p;
            p = ((unsigned long long)fkey(v.w) << 32) | (rb | (c0 + 3)); if (p < m3) m3 = p;
        }
        atomicMin(&s_ckey[c0 + 0], m0);
        atomicMin(&s_ckey[c0 + 1], m1);
        atomicMin(&s_ckey[c0 + 2], m2);
        atomicMin(&s_ckey[c0 + 3], m3);
    }
    __syncthreads();
    if (wid != 0) return;

    // ---- warp 0: register-resident state ----
    unsigned long long slot[4];
    #pragma unroll
    for (int s = 0; s < 4; s++)
        slot[s] = (lane < 25) ? s_ckey[lane * 4 + s] : ~0ull;
    unsigned mrow = 0;

    float* ro = rows_out + b * T_;
    float* co = cols_out + b * T_;

    for (int step = 0; step < T_; step++) {
        // local min over 4 slots (u64 compare == (key,row,col) lex order)
        unsigned long long m = slot[0];
        if (slot[1] < m) m = slot[1];
        if (slot[2] < m) m = slot[2];
        if (slot[3] < m) m = slot[3];

        unsigned k  = (unsigned)(m >> 32);
        unsigned mk = redux_min_u32(k);
        unsigned tag = (k == mk) ? (unsigned)m : 0xFFFFFFFFu;
        unsigned mt  = redux_min_u32(tag);

        const int r = (int)(mt >> 7);
        const int c = (int)(mt & 0x7Fu);

        if (lane == 0) { ro[step] = (float)r; co[step] = (float)c; }
        if (lane == (r & 31)) mrow |= 1u << (r >> 5);
        if (lane == (c >> 2)) slot[c & 3] = ~0ull;   // remove matched column

        if (step == T_ - 1) break;

        // columns whose cached min row was just matched need a rescan
        bool n0 = ((int)((slot[0] >> 7) & 0x3FFu) == r);
        bool n1 = ((int)((slot[1] >> 7) & 0x3FFu) == r);
        bool n2 = ((int)((slot[2] >> 7) & 0x3FFu) == r);
        bool n3 = ((int)((slot[3] >> 7) & 0x3FFu) == r);
        unsigned any = __ballot_sync(FULLM, n0 | n1 | n2 | n3);
        if (any == 0) continue;   // common case

        #pragma unroll
        for (int s = 0; s < 4; s++) {
            bool ns = (s == 0) ? n0 : (s == 1) ? n1 : (s == 2) ? n2 : n3;
            unsigned need = __ballot_sync(FULLM, ns);
            while (need) {
                int ln = __ffs(need) - 1;
                need &= need - 1;
                int cc = __shfl_sync(FULLM, (int)(slot[s] & 0x7Fu), ln);
                const float* colp = Cb + cc;
                unsigned long long best = ~0ull;
                for (int i = 0, rr = lane; rr < Q_; i++, rr += 32) {
                    if (!((mrow >> i) & 1u)) {
                        unsigned long long p =
                            ((unsigned long long)fkey(colp[(size_t)rr * BT_]) << 32)
                            | (unsigned)((rr << 7) | cc);
                        if (p < best) best = p;
                    }
                }
                unsigned bk  = (unsigned)(best >> 32);
                unsigned mbk = redux_min_u32(bk);
                unsigned bt  = (bk == mbk) ? (unsigned)best : 0xFFFFFFFFu;
                unsigned mbt = redux_min_u32(bt);
                if (lane == ln)
                    slot[s] = ((unsigned long long)mbk << 32) | mbt;
            }
        }
    }
}

// ---------------------------------------------------------------------------
extern "C" void kernel_launch(void* const* d_in, const int* in_sizes, int n_in,
                              void* d_out, int out_size)
{
    const float* logits     = (const float*)d_in[0];
    const float* pred_boxes = (const float*)d_in[1];
    const int*   tgt_labels = (const int*)  d_in[2];
    const float* tgt_boxes  = (const float*)d_in[3];
    float* out = (float*)d_out;

    cudaFuncSetAttribute(cost_kernel,
                         cudaFuncAttributeMaxDynamicSharedMemorySize, SMEM_COST);

    cost_kernel<<<BQ_ / RPB, COST_THREADS, SMEM_COST>>>(
        logits, pred_boxes, tgt_labels, tgt_boxes, out);

    greedy_kernel<<<B_, 1024>>>(
        out, out + COST_ELEMS, out + COST_ELEMS + B_ * T_);
}